// round 2
// baseline (speedup 1.0000x reference)
#include <cuda_runtime.h>
#include <math.h>

// Problem constants
#define B_    2
#define S_    1024
#define H_    4096
#define NH_   32
#define HD_   128
#define M_    (B_ * S_)        // 2048 rows
#define NQKV_ (3 * H_)         // 12288

// Scratch (device globals — no runtime allocation allowed)
__device__ float g_qkv[(size_t)M_ * NQKV_];   // ~100.7 MB
__device__ float g_ctx[(size_t)M_ * H_];      // ~33.6 MB

// ============================================================
// SGEMM: C[M,N] = A[M,K] @ W[K,N] + bias (+ residual)
// 128x128 block tile, BK=16, 256 threads, 8x8 per-thread tile
// ============================================================
#define BM 128
#define BN 128
#define BK 16
#define TM 8
#define TN 8

template<bool RES>
__global__ __launch_bounds__(256)
void sgemm_kernel(const float* __restrict__ A, const float* __restrict__ W,
                  const float* __restrict__ bias, const float* __restrict__ res,
                  float* __restrict__ C, int N, int K)
{
    __shared__ float As[BK][BM];   // transposed A tile
    __shared__ float Bs[BK][BN];

    const int tid = threadIdx.x;
    const int tx  = tid & 15;      // 0..15 -> N direction
    const int ty  = tid >> 4;      // 0..15 -> M direction
    const int row0 = blockIdx.y * BM;
    const int col0 = blockIdx.x * BN;

    // A tile load map: 128 rows x 16 k, float4 per thread, 2 iterations
    const int aRow = tid >> 2;            // 0..63
    const int aCol = (tid & 3) << 2;      // 0,4,8,12
    // B tile load map: 16 k x 128 cols, float4 per thread, 2 iterations
    const int bRow = tid >> 5;            // 0..7
    const int bCol = (tid & 31) << 2;     // 0..124

    float acc[TM][TN];
#pragma unroll
    for (int i = 0; i < TM; i++)
#pragma unroll
        for (int j = 0; j < TN; j++) acc[i][j] = 0.f;

    for (int k0 = 0; k0 < K; k0 += BK) {
#pragma unroll
        for (int it = 0; it < 2; it++) {
            int r = aRow + it * 64;
            float4 v = *(const float4*)(A + (size_t)(row0 + r) * K + k0 + aCol);
            As[aCol + 0][r] = v.x;
            As[aCol + 1][r] = v.y;
            As[aCol + 2][r] = v.z;
            As[aCol + 3][r] = v.w;
        }
#pragma unroll
        for (int it = 0; it < 2; it++) {
            int r = bRow + it * 8;
            *(float4*)(&Bs[r][bCol]) =
                *(const float4*)(W + (size_t)(k0 + r) * N + col0 + bCol);
        }
        __syncthreads();

#pragma unroll
        for (int kk = 0; kk < BK; kk++) {
            float a[TM], b[TN];
            *(float4*)&a[0] = *(const float4*)&As[kk][ty * TM];
            *(float4*)&a[4] = *(const float4*)&As[kk][ty * TM + 4];
            *(float4*)&b[0] = *(const float4*)&Bs[kk][tx * TN];
            *(float4*)&b[4] = *(const float4*)&Bs[kk][tx * TN + 4];
#pragma unroll
            for (int i = 0; i < TM; i++)
#pragma unroll
                for (int j = 0; j < TN; j++) acc[i][j] += a[i] * b[j];
        }
        __syncthreads();
    }

#pragma unroll
    for (int i = 0; i < TM; i++) {
        int r = row0 + ty * TM + i;
#pragma unroll
        for (int j = 0; j < TN; j += 4) {
            int c = col0 + tx * TN + j;
            float4 v;
            v.x = acc[i][j + 0] + bias[c + 0];
            v.y = acc[i][j + 1] + bias[c + 1];
            v.z = acc[i][j + 2] + bias[c + 2];
            v.w = acc[i][j + 3] + bias[c + 3];
            if (RES) {
                float4 rv = *(const float4*)(res + (size_t)r * N + c);
                v.x += rv.x; v.y += rv.y; v.z += rv.z; v.w += rv.w;
            }
            *(float4*)(C + (size_t)r * N + c) = v;
        }
    }
}

// ============================================================
// Flash-style causal attention with ALiBi.
// One block per (q-tile of 64, batch*head). 256 threads.
// Thread (ty,tx): S fragment rows ty*4..+3, cols tx*4..+3;
//                 O fragment rows ty*4..+3, cols tx*8..+7.
// ============================================================
#define AM 64
#define AN 64
#define QSTR 132    // 64 x 132 floats, padded (row-major [token][d])
#define KSTR 129    // K tile stored [token][d], odd stride to spread banks
#define VSTR 132    // V tile stored [token][d]
#define PSTR 65     // P tile [q][k]
#define ATTN_SMEM_FLOATS (AM * QSTR + AM * VSTR + AM * PSTR)
#define ATTN_SMEM_BYTES  (ATTN_SMEM_FLOATS * 4)   // 84224 B

__global__ __launch_bounds__(256)
void attn_kernel(const float* __restrict__ qkv, const float* __restrict__ alibi,
                 float* __restrict__ ctx)
{
    extern __shared__ float sh[];
    float* Qs  = sh;                 // [AM][QSTR]
    float* KVs = sh + AM * QSTR;     // K: [AN][KSTR]  then reused as V: [AN][VSTR]
    float* Ps  = KVs + AM * VSTR;    // [AM][PSTR]

    const int qt  = blockIdx.x;
    const int bh  = blockIdx.y;
    const int b   = bh >> 5;
    const int h   = bh & 31;
    const int tid = threadIdx.x;
    const int tx  = tid & 15;
    const int ty  = tid >> 4;

    const size_t rowbase = (size_t)b * S_;
    const int qcol = h * 384;                 // q at +0, k at +128, v at +256
    const float* al = alibi + (size_t)bh * S_;
    const float inv = 0.08838834764831845f;   // 1/sqrt(128)

    // Load Q tile (coalesced float4)
    for (int i = tid; i < AM * 32; i += 256) {
        int t = i >> 5, dg = (i & 31) << 2;
        float4 v = *(const float4*)(qkv + (rowbase + qt * AM + t) * NQKV_ + qcol + dg);
        *(float4*)(Qs + t * QSTR + dg) = v;
    }

    float m_i[4], l_i[4], acc[4][8];
#pragma unroll
    for (int i = 0; i < 4; i++) {
        m_i[i] = -1e30f; l_i[i] = 0.f;
#pragma unroll
        for (int c = 0; c < 8; c++) acc[i][c] = 0.f;
    }
    __syncthreads();

    for (int j = 0; j <= qt; j++) {
        // --- Load K tile into KVs (stride KSTR) ---
        for (int i = tid; i < AN * 32; i += 256) {
            int t = i >> 5, dg = (i & 31) << 2;
            float4 v = *(const float4*)(qkv + (rowbase + j * AN + t) * NQKV_ + qcol + HD_ + dg);
            float* p = KVs + t * KSTR + dg;
            p[0] = v.x; p[1] = v.y; p[2] = v.z; p[3] = v.w;
        }
        __syncthreads();

        // --- S = Q K^T (4x4 per thread) ---
        float s[4][4];
#pragma unroll
        for (int i = 0; i < 4; i++)
#pragma unroll
            for (int j2 = 0; j2 < 4; j2++) s[i][j2] = 0.f;

        const float* qb = Qs + (ty * 4) * QSTR;
        const float* kb = KVs + (tx * 4) * KSTR;
#pragma unroll 4
        for (int kk = 0; kk < HD_; kk++) {
            float qv[4], kv[4];
#pragma unroll
            for (int i = 0; i < 4; i++) qv[i] = qb[i * QSTR + kk];
#pragma unroll
            for (int j2 = 0; j2 < 4; j2++) kv[j2] = kb[j2 * KSTR + kk];
#pragma unroll
            for (int i = 0; i < 4; i++)
#pragma unroll
                for (int j2 = 0; j2 < 4; j2++) s[i][j2] += qv[i] * kv[j2];
        }

        // --- scale + alibi + causal mask ---
        const bool diag = (j == qt);
#pragma unroll
        for (int i = 0; i < 4; i++) {
            int ql = ty * 4 + i;
#pragma unroll
            for (int j2 = 0; j2 < 4; j2++) {
                int kl = tx * 4 + j2;
                float v = s[i][j2] * inv + al[j * AN + kl];
                if (diag && kl > ql) v = -1e30f;
                s[i][j2] = v;
            }
        }

        // --- online softmax (row reduce across the 16 lanes sharing ty) ---
#pragma unroll
        for (int i = 0; i < 4; i++) {
            float rm = fmaxf(fmaxf(s[i][0], s[i][1]), fmaxf(s[i][2], s[i][3]));
#pragma unroll
            for (int off = 8; off > 0; off >>= 1)
                rm = fmaxf(rm, __shfl_xor_sync(0xffffffffu, rm, off));
            float mnew  = fmaxf(m_i[i], rm);
            float scale = __expf(m_i[i] - mnew);
            float rs = 0.f;
#pragma unroll
            for (int j2 = 0; j2 < 4; j2++) {
                float p = __expf(s[i][j2] - mnew);
                Ps[(ty * 4 + i) * PSTR + tx * 4 + j2] = p;
                rs += p;
            }
#pragma unroll
            for (int off = 8; off > 0; off >>= 1)
                rs += __shfl_xor_sync(0xffffffffu, rs, off);
            l_i[i] = l_i[i] * scale + rs;
            m_i[i] = mnew;
#pragma unroll
            for (int c = 0; c < 8; c++) acc[i][c] *= scale;
        }
        __syncthreads();   // P written; K reads done -> safe to overwrite with V

        // --- Load V tile into KVs (stride VSTR, float4) ---
        for (int i = tid; i < AN * 32; i += 256) {
            int t = i >> 5, dg = (i & 31) << 2;
            float4 v = *(const float4*)(qkv + (rowbase + j * AN + t) * NQKV_ + qcol + 2 * HD_ + dg);
            *(float4*)(KVs + t * VSTR + dg) = v;
        }
        __syncthreads();

        // --- O += P @ V ---
        const float* pb = Ps + (ty * 4) * PSTR;
        const float* vb = KVs + tx * 8;
#pragma unroll 2
        for (int kk = 0; kk < AN; kk++) {
            float pv[4];
#pragma unroll
            for (int i = 0; i < 4; i++) pv[i] = pb[i * PSTR + kk];
            float vv[8];
            *(float4*)&vv[0] = *(const float4*)(vb + kk * VSTR);
            *(float4*)&vv[4] = *(const float4*)(vb + kk * VSTR + 4);
#pragma unroll
            for (int i = 0; i < 4; i++)
#pragma unroll
                for (int c = 0; c < 8; c++) acc[i][c] += pv[i] * vv[c];
        }
        __syncthreads();   // before next iteration's K load overwrites V
    }

    // --- write ctx in (b, s, nh*hd) layout ---
#pragma unroll
    for (int i = 0; i < 4; i++) {
        float linv = 1.f / l_i[i];
        size_t orow = (rowbase + qt * AM + ty * 4 + i) * H_ + (size_t)h * HD_ + tx * 8;
#pragma unroll
        for (int c = 0; c < 8; c++) ctx[orow + c] = acc[i][c] * linv;
    }
}

// ============================================================
// Launch
// ============================================================
extern "C" void kernel_launch(void* const* d_in, const int* in_sizes, int n_in,
                              void* d_out, int out_size)
{
    const float* hidden   = (const float*)d_in[0];
    const float* residual = (const float*)d_in[1];
    const float* alibi    = (const float*)d_in[2];
    // d_in[3] = attention_mask (causal; derived analytically) - unused
    const float* Wqkv     = (const float*)d_in[4];
    const float* bqkv     = (const float*)d_in[5];
    const float* Wd       = (const float*)d_in[6];
    const float* bd       = (const float*)d_in[7];
    // d_in[8] = num_heads (compile-time constant) - unused
    float* out = (float*)d_out;

    void *qkvp, *ctxp;
    cudaGetSymbolAddress(&qkvp, g_qkv);
    cudaGetSymbolAddress(&ctxp, g_ctx);
    float* qkv = (float*)qkvp;
    float* ctx = (float*)ctxp;

    cudaFuncSetAttribute(attn_kernel,
                         cudaFuncAttributeMaxDynamicSharedMemorySize,
                         ATTN_SMEM_BYTES);

    dim3 blk(256);

    // 1) fused QKV projection: [2048,4096] @ [4096,12288] + bias
    sgemm_kernel<false><<<dim3(NQKV_ / BN, M_ / BM), blk>>>(
        hidden, Wqkv, bqkv, nullptr, qkv, NQKV_, H_);

    // 2) causal attention with ALiBi -> ctx [2048, 4096]
    attn_kernel<<<dim3(S_ / AM, B_ * NH_), blk, ATTN_SMEM_BYTES>>>(qkv, alibi, ctx);

    // 3) dense projection + bias + residual
    sgemm_kernel<true><<<dim3(H_ / BN, M_ / BM), blk>>>(
        ctx, Wd, bd, residual, out, H_, H_);
}

// round 4
// speedup vs baseline: 2.5017x; 2.5017x over previous
#include <cuda_runtime.h>
#include <cuda_bf16.h>
#include <stdint.h>
#include <math.h>

// Problem constants
#define B_    2
#define S_    1024
#define H_    4096
#define NH_   32
#define HD_   128
#define M_    2048
#define NQKV_ 12288

// ---------------- device scratch (no runtime allocation) ----------------
__device__ float g_qkv[(size_t)M_ * NQKV_];
__device__ float g_ctx[(size_t)M_ * H_];
__device__ __nv_bfloat16 g_Ah[(size_t)M_ * H_];
__device__ __nv_bfloat16 g_Al[(size_t)M_ * H_];
__device__ __nv_bfloat16 g_Bqh[(size_t)NQKV_ * H_];
__device__ __nv_bfloat16 g_Bql[(size_t)NQKV_ * H_];
__device__ __nv_bfloat16 g_Bdh[(size_t)H_ * H_];
__device__ __nv_bfloat16 g_Bdl[(size_t)H_ * H_];
__device__ __nv_bfloat16 g_Ch[(size_t)M_ * H_];
__device__ __nv_bfloat16 g_Cl[(size_t)M_ * H_];

// ---------------- PTX helpers (all portable, non-'a' features) ----------------
__device__ __forceinline__ uint32_t smem_u32(const void* p) {
    uint32_t a;
    asm("{ .reg .u64 t; cvta.to.shared.u64 t, %1; cvt.u32.u64 %0, t; }" : "=r"(a) : "l"(p));
    return a;
}
__device__ __forceinline__ void cp_async16(uint32_t dst_smem, const void* src) {
    asm volatile("cp.async.cg.shared.global [%0], [%1], 16;"
                 :: "r"(dst_smem), "l"(src) : "memory");
}
__device__ __forceinline__ void cp_commit() {
    asm volatile("cp.async.commit_group;" ::: "memory");
}
__device__ __forceinline__ void cp_wait1() {
    asm volatile("cp.async.wait_group 1;" ::: "memory");
}
__device__ __forceinline__ void ldsm4(uint32_t* r, uint32_t addr) {
    asm volatile("ldmatrix.sync.aligned.m8n8.x4.shared.b16 {%0,%1,%2,%3}, [%4];"
                 : "=r"(r[0]), "=r"(r[1]), "=r"(r[2]), "=r"(r[3]) : "r"(addr));
}
__device__ __forceinline__ void mma_bf16(float* d, const uint32_t* a, const uint32_t* b) {
    asm volatile(
        "mma.sync.aligned.m16n8k16.row.col.f32.bf16.bf16.f32 "
        "{%0,%1,%2,%3}, {%4,%5,%6,%7}, {%8,%9}, {%0,%1,%2,%3};"
        : "+f"(d[0]), "+f"(d[1]), "+f"(d[2]), "+f"(d[3])
        : "r"(a[0]), "r"(a[1]), "r"(a[2]), "r"(a[3]), "r"(b[0]), "r"(b[1]));
}

// ---------------- split helpers ----------------
__device__ __forceinline__ void split1(float f, __nv_bfloat16& h, __nv_bfloat16& l) {
    h = __float2bfloat16(f);
    l = __float2bfloat16(f - __bfloat162float(h));
}

__global__ __launch_bounds__(256)
void split_rows(const float* __restrict__ in, __nv_bfloat16* __restrict__ hi,
                __nv_bfloat16* __restrict__ lo, int n4)
{
    int i = blockIdx.x * 256 + threadIdx.x;
    if (i >= n4) return;
    float4 v = ((const float4*)in)[i];
    __nv_bfloat16 h0, h1, h2, h3, l0, l1, l2, l3;
    split1(v.x, h0, l0); split1(v.y, h1, l1); split1(v.z, h2, l2); split1(v.w, h3, l3);
    __nv_bfloat162* hp = (__nv_bfloat162*)hi;
    __nv_bfloat162* lp = (__nv_bfloat162*)lo;
    hp[2 * i]     = __nv_bfloat162(h0, h1);
    hp[2 * i + 1] = __nv_bfloat162(h2, h3);
    lp[2 * i]     = __nv_bfloat162(l0, l1);
    lp[2 * i + 1] = __nv_bfloat162(l2, l3);
}

// W [K][N] fp32 -> B [N][K] bf16 hi/lo (transpose + split)
__global__ __launch_bounds__(256)
void split_transpose(const float* __restrict__ W, __nv_bfloat16* __restrict__ Bh,
                     __nv_bfloat16* __restrict__ Bl, int K, int N)
{
    __shared__ float ts[32][33];
    int n0 = blockIdx.x * 32, k0 = blockIdx.y * 32;
    int tx = threadIdx.x, ty = threadIdx.y;  // (32, 8)
#pragma unroll
    for (int i = 0; i < 4; i++)
        ts[ty + i * 8][tx] = W[(size_t)(k0 + ty + i * 8) * N + n0 + tx];
    __syncthreads();
#pragma unroll
    for (int i = 0; i < 4; i++) {
        float f = ts[tx][ty + i * 8];
        __nv_bfloat16 h, l;
        split1(f, h, l);
        size_t o = (size_t)(n0 + ty + i * 8) * K + k0 + tx;
        Bh[o] = h;
        Bl[o] = l;
    }
}

// ============================================================
// mma.sync split-bf16 GEMM: C[M,N] = A[M,K] @ B^T + bias (+res)
// A [M][K] hi/lo bf16, B [N][K] hi/lo bf16. 128x128 CTA tile,
// BK=32, 8 warps (2x4), warp tile 64x32, 3-stage cp.async.
// SMEM tile: [128 rows][32 k] bf16 = 64B rows; 16B chunk c
// swizzled: c ^= (row>>1)&3  (conflict-free for ldmatrix + STS)
// ============================================================
#define STAGE_BYTES 32768               // 4 tiles x 8192B (Ah,Al,Bh,Bl)
#define GSTAGES 3
#define GSM_TOTAL (GSTAGES * STAGE_BYTES)   // 98304 B

template<bool RES>
__global__ __launch_bounds__(256, 1)
void mma_gemm(const __nv_bfloat16* __restrict__ Ah, const __nv_bfloat16* __restrict__ Al,
              const __nv_bfloat16* __restrict__ Bh, const __nv_bfloat16* __restrict__ Bl,
              const float* __restrict__ bias, const float* __restrict__ res,
              float* __restrict__ C, int N, int K)
{
    extern __shared__ __align__(1024) char smem[];
    const uint32_t sb = smem_u32(smem);
    const int tid  = threadIdx.x;
    const int lane = tid & 31;
    const int warp = tid >> 5;
    const int wm = warp >> 2;            // 0..1  (M)
    const int wn = warp & 3;             // 0..3  (N)
    const int row0 = blockIdx.x * 128;   // M fast-varying -> B tiles L2-resident
    const int col0 = blockIdx.y * 128;

    // ldmatrix per-lane addressing
    // A: lane l -> row (l&15), k-half (l>>4)
    const int aRow = wm * 64 + (lane & 15);
    const uint32_t aSw = (uint32_t)((aRow >> 1) & 3);
    const uint32_t aCH = (uint32_t)(lane >> 4);
    // B: lane l -> n row = p*16 + ((l>>4)&1)*8 + (l&7), k-half (l>>3)&1
    const int bRow = wn * 32 + (((lane >> 4) & 1) << 3) + (lane & 7);
    const uint32_t bSw = (uint32_t)((bRow >> 1) & 3);
    const uint32_t bCH = (uint32_t)((lane >> 3) & 1);

    float acc[4][4][4];
#pragma unroll
    for (int mt = 0; mt < 4; mt++)
#pragma unroll
        for (int nt = 0; nt < 4; nt++)
#pragma unroll
            for (int e = 0; e < 4; e++) acc[mt][nt][e] = 0.f;

    // cp.async load map: 2048 16B chunks/stage, 8 per thread.
    // it>>1 selects tile (0=Ah,1=Al,2=Bh,3=Bl); row=(it&1)*64+tid>>2; c=tid&3
    const int ldRowA = row0 + (tid >> 2);
    const int ldRowB = col0 + (tid >> 2);
    const int ldC    = tid & 3;
    const uint32_t ldSw = ((uint32_t)(tid >> 2) * 64) ^
                          (((uint32_t)ldC ^ (((uint32_t)(tid >> 2) >> 1) & 3)) << 4);
    // second half (rows +64)
    const uint32_t ldSw2 = (((uint32_t)(tid >> 2) + 64) * 64) ^
                           (((uint32_t)ldC ^ ((((uint32_t)(tid >> 2) + 64) >> 1) & 3)) << 4);

    const int NK = K / 32;

    auto load_stage = [&](int s, int k0) {
        uint32_t base = sb + (uint32_t)s * STAGE_BYTES;
        const __nv_bfloat16* gA0 = Ah + (size_t)ldRowA * K + k0 + ldC * 8;
        const __nv_bfloat16* gA1 = Al + (size_t)ldRowA * K + k0 + ldC * 8;
        const __nv_bfloat16* gB0 = Bh + (size_t)ldRowB * K + k0 + ldC * 8;
        const __nv_bfloat16* gB1 = Bl + (size_t)ldRowB * K + k0 + ldC * 8;
        const size_t off64 = (size_t)64 * K;
        cp_async16(base + ldSw,                gA0);
        cp_async16(base + ldSw2,               gA0 + off64);
        cp_async16(base + 8192  + ldSw,        gA1);
        cp_async16(base + 8192  + ldSw2,       gA1 + off64);
        cp_async16(base + 16384 + ldSw,        gB0);
        cp_async16(base + 16384 + ldSw2,       gB0 + off64);
        cp_async16(base + 24576 + ldSw,        gB1);
        cp_async16(base + 24576 + ldSw2,       gB1 + off64);
    };

    load_stage(0, 0);  cp_commit();
    load_stage(1, 32); cp_commit();

    int st = 0;
    for (int kt = 0; kt < NK; kt++) {
        cp_wait1();
        __syncthreads();

        uint32_t base = sb + (uint32_t)st * STAGE_BYTES;
        uint32_t aHiB = base +         (uint32_t)aRow * 64;
        uint32_t aLoB = aHiB + 8192;
        uint32_t bHiB = base + 16384 + (uint32_t)bRow * 64;
        uint32_t bLoB = bHiB + 8192;

#pragma unroll
        for (int k = 0; k < 2; k++) {
            const uint32_t ka = ((2u * k + aCH) ^ aSw) << 4;
            const uint32_t kb = ((2u * k + bCH) ^ bSw) << 4;
            uint32_t ahi[4][4], bhi[2][4];
#pragma unroll
            for (int mt = 0; mt < 4; mt++) ldsm4(ahi[mt], aHiB + mt * 1024 + ka);
#pragma unroll
            for (int p = 0; p < 2; p++)    ldsm4(bhi[p], bHiB + p * 1024 + kb);
            // term 1: Ahi x Bhi
#pragma unroll
            for (int mt = 0; mt < 4; mt++)
#pragma unroll
                for (int nt = 0; nt < 4; nt++)
                    mma_bf16(acc[mt][nt], ahi[mt], &bhi[nt >> 1][(nt & 1) * 2]);
            // term 2: Ahi x Blo
            uint32_t blo[2][4];
#pragma unroll
            for (int p = 0; p < 2; p++) ldsm4(blo[p], bLoB + p * 1024 + kb);
#pragma unroll
            for (int mt = 0; mt < 4; mt++)
#pragma unroll
                for (int nt = 0; nt < 4; nt++)
                    mma_bf16(acc[mt][nt], ahi[mt], &blo[nt >> 1][(nt & 1) * 2]);
            // term 3: Alo x Bhi
            uint32_t alo[4][4];
#pragma unroll
            for (int mt = 0; mt < 4; mt++) ldsm4(alo[mt], aLoB + mt * 1024 + ka);
#pragma unroll
            for (int mt = 0; mt < 4; mt++)
#pragma unroll
                for (int nt = 0; nt < 4; nt++)
                    mma_bf16(acc[mt][nt], alo[mt], &bhi[nt >> 1][(nt & 1) * 2]);
        }

        if (kt + 2 < NK) load_stage((st + 2) % GSTAGES, (kt + 2) * 32);
        cp_commit();
        st = (st + 1) % GSTAGES;
    }

    // Epilogue: direct float2 stores with bias (+residual)
    const int g  = lane >> 2;
    const int i4 = lane & 3;
#pragma unroll
    for (int mt = 0; mt < 4; mt++) {
        int r = row0 + wm * 64 + mt * 16 + g;
#pragma unroll
        for (int nt = 0; nt < 4; nt++) {
            int c = col0 + wn * 32 + nt * 8 + i4 * 2;
            float2 bv = *(const float2*)(bias + c);
            size_t o0 = (size_t)r * N + c;
            size_t o1 = (size_t)(r + 8) * N + c;
            float2 v0, v1;
            v0.x = acc[mt][nt][0] + bv.x; v0.y = acc[mt][nt][1] + bv.y;
            v1.x = acc[mt][nt][2] + bv.x; v1.y = acc[mt][nt][3] + bv.y;
            if (RES) {
                float2 r0 = *(const float2*)(res + o0);
                float2 r1 = *(const float2*)(res + o1);
                v0.x += r0.x; v0.y += r0.y;
                v1.x += r1.x; v1.y += r1.y;
            }
            *(float2*)(C + o0) = v0;
            *(float2*)(C + o1) = v1;
        }
    }
}

// ============================================================
// Flash-style causal attention with ALiBi (fp32 SIMT, unchanged)
// ============================================================
#define AM 64
#define AN 64
#define QSTR 132
#define KSTR 129
#define VSTR 132
#define PSTR 65
#define ATTN_SMEM_FLOATS (AM * QSTR + AM * VSTR + AM * PSTR)
#define ATTN_SMEM_BYTES  (ATTN_SMEM_FLOATS * 4)

__global__ __launch_bounds__(256)
void attn_kernel(const float* __restrict__ qkv, const float* __restrict__ alibi,
                 float* __restrict__ ctx)
{
    extern __shared__ float sh[];
    float* Qs  = sh;
    float* KVs = sh + AM * QSTR;
    float* Ps  = KVs + AM * VSTR;

    const int qt  = blockIdx.x;
    const int bh  = blockIdx.y;
    const int b   = bh >> 5;
    const int h   = bh & 31;
    const int tid = threadIdx.x;
    const int tx  = tid & 15;
    const int ty  = tid >> 4;

    const size_t rowbase = (size_t)b * S_;
    const int qcol = h * 384;
    const float* al = alibi + (size_t)bh * S_;
    const float inv = 0.08838834764831845f;

    for (int i = tid; i < AM * 32; i += 256) {
        int t = i >> 5, dg = (i & 31) << 2;
        float4 v = *(const float4*)(qkv + (rowbase + qt * AM + t) * NQKV_ + qcol + dg);
        *(float4*)(Qs + t * QSTR + dg) = v;
    }

    float m_i[4], l_i[4], acc[4][8];
#pragma unroll
    for (int i = 0; i < 4; i++) {
        m_i[i] = -1e30f; l_i[i] = 0.f;
#pragma unroll
        for (int c = 0; c < 8; c++) acc[i][c] = 0.f;
    }
    __syncthreads();

    for (int j = 0; j <= qt; j++) {
        for (int i = tid; i < AN * 32; i += 256) {
            int t = i >> 5, dg = (i & 31) << 2;
            float4 v = *(const float4*)(qkv + (rowbase + j * AN + t) * NQKV_ + qcol + HD_ + dg);
            float* p = KVs + t * KSTR + dg;
            p[0] = v.x; p[1] = v.y; p[2] = v.z; p[3] = v.w;
        }
        __syncthreads();

        float s[4][4];
#pragma unroll
        for (int i = 0; i < 4; i++)
#pragma unroll
            for (int j2 = 0; j2 < 4; j2++) s[i][j2] = 0.f;

        const float* qb = Qs + (ty * 4) * QSTR;
        const float* kb = KVs + (tx * 4) * KSTR;
#pragma unroll 4
        for (int kk = 0; kk < HD_; kk++) {
            float qv[4], kv[4];
#pragma unroll
            for (int i = 0; i < 4; i++) qv[i] = qb[i * QSTR + kk];
#pragma unroll
            for (int j2 = 0; j2 < 4; j2++) kv[j2] = kb[j2 * KSTR + kk];
#pragma unroll
            for (int i = 0; i < 4; i++)
#pragma unroll
                for (int j2 = 0; j2 < 4; j2++) s[i][j2] += qv[i] * kv[j2];
        }

        const bool diag = (j == qt);
#pragma unroll
        for (int i = 0; i < 4; i++) {
            int ql = ty * 4 + i;
#pragma unroll
            for (int j2 = 0; j2 < 4; j2++) {
                int kl = tx * 4 + j2;
                float v = s[i][j2] * inv + al[j * AN + kl];
                if (diag && kl > ql) v = -1e30f;
                s[i][j2] = v;
            }
        }

#pragma unroll
        for (int i = 0; i < 4; i++) {
            float rm = fmaxf(fmaxf(s[i][0], s[i][1]), fmaxf(s[i][2], s[i][3]));
#pragma unroll
            for (int off = 8; off > 0; off >>= 1)
                rm = fmaxf(rm, __shfl_xor_sync(0xffffffffu, rm, off));
            float mnew  = fmaxf(m_i[i], rm);
            float scale = __expf(m_i[i] - mnew);
            float rs = 0.f;
#pragma unroll
            for (int j2 = 0; j2 < 4; j2++) {
                float p = __expf(s[i][j2] - mnew);
                Ps[(ty * 4 + i) * PSTR + tx * 4 + j2] = p;
                rs += p;
            }
#pragma unroll
            for (int off = 8; off > 0; off >>= 1)
                rs += __shfl_xor_sync(0xffffffffu, rs, off);
            l_i[i] = l_i[i] * scale + rs;
            m_i[i] = mnew;
#pragma unroll
            for (int c = 0; c < 8; c++) acc[i][c] *= scale;
        }
        __syncthreads();

        for (int i = tid; i < AN * 32; i += 256) {
            int t = i >> 5, dg = (i & 31) << 2;
            float4 v = *(const float4*)(qkv + (rowbase + j * AN + t) * NQKV_ + qcol + 2 * HD_ + dg);
            *(float4*)(KVs + t * VSTR + dg) = v;
        }
        __syncthreads();

        const float* pb = Ps + (ty * 4) * PSTR;
        const float* vb = KVs + tx * 8;
#pragma unroll 2
        for (int kk = 0; kk < AN; kk++) {
            float pv[4];
#pragma unroll
            for (int i = 0; i < 4; i++) pv[i] = pb[i * PSTR + kk];
            float vv[8];
            *(float4*)&vv[0] = *(const float4*)(vb + kk * VSTR);
            *(float4*)&vv[4] = *(const float4*)(vb + kk * VSTR + 4);
#pragma unroll
            for (int i = 0; i < 4; i++)
#pragma unroll
                for (int c = 0; c < 8; c++) acc[i][c] += pv[i] * vv[c];
        }
        __syncthreads();
    }

#pragma unroll
    for (int i = 0; i < 4; i++) {
        float linv = 1.f / l_i[i];
        size_t orow = (rowbase + qt * AM + ty * 4 + i) * H_ + (size_t)h * HD_ + tx * 8;
#pragma unroll
        for (int c = 0; c < 8; c++) ctx[orow + c] = acc[i][c] * linv;
    }
}

// ============================================================
// Launch
// ============================================================
extern "C" void kernel_launch(void* const* d_in, const int* in_sizes, int n_in,
                              void* d_out, int out_size)
{
    const float* hidden   = (const float*)d_in[0];
    const float* residual = (const float*)d_in[1];
    const float* alibi    = (const float*)d_in[2];
    const float* Wqkv     = (const float*)d_in[4];
    const float* bqkv     = (const float*)d_in[5];
    const float* Wd       = (const float*)d_in[6];
    const float* bd       = (const float*)d_in[7];
    float* out = (float*)d_out;

    void* p;
    cudaGetSymbolAddress(&p, g_qkv); float* qkv = (float*)p;
    cudaGetSymbolAddress(&p, g_ctx); float* ctx = (float*)p;
    cudaGetSymbolAddress(&p, g_Ah);  __nv_bfloat16* Ah  = (__nv_bfloat16*)p;
    cudaGetSymbolAddress(&p, g_Al);  __nv_bfloat16* Al  = (__nv_bfloat16*)p;
    cudaGetSymbolAddress(&p, g_Bqh); __nv_bfloat16* Bqh = (__nv_bfloat16*)p;
    cudaGetSymbolAddress(&p, g_Bql); __nv_bfloat16* Bql = (__nv_bfloat16*)p;
    cudaGetSymbolAddress(&p, g_Bdh); __nv_bfloat16* Bdh = (__nv_bfloat16*)p;
    cudaGetSymbolAddress(&p, g_Bdl); __nv_bfloat16* Bdl = (__nv_bfloat16*)p;
    cudaGetSymbolAddress(&p, g_Ch);  __nv_bfloat16* Ch  = (__nv_bfloat16*)p;
    cudaGetSymbolAddress(&p, g_Cl);  __nv_bfloat16* Cl  = (__nv_bfloat16*)p;

    cudaFuncSetAttribute(attn_kernel, cudaFuncAttributeMaxDynamicSharedMemorySize, ATTN_SMEM_BYTES);
    cudaFuncSetAttribute(mma_gemm<false>, cudaFuncAttributeMaxDynamicSharedMemorySize, GSM_TOTAL);
    cudaFuncSetAttribute(mma_gemm<true>,  cudaFuncAttributeMaxDynamicSharedMemorySize, GSM_TOTAL);

    // 0) split inputs to bf16 hi/lo
    split_rows<<<(M_ * H_ / 4 + 255) / 256, 256>>>(hidden, Ah, Al, M_ * H_ / 4);
    split_transpose<<<dim3(NQKV_ / 32, H_ / 32), dim3(32, 8)>>>(Wqkv, Bqh, Bql, H_, NQKV_);
    split_transpose<<<dim3(H_ / 32, H_ / 32), dim3(32, 8)>>>(Wd, Bdh, Bdl, H_, H_);

    // 1) QKV projection: [2048,12288] = A @ Wqkv + b
    mma_gemm<false><<<dim3(M_ / 128, NQKV_ / 128), 256, GSM_TOTAL>>>(
        Ah, Al, Bqh, Bql, bqkv, nullptr, qkv, NQKV_, H_);

    // 2) attention -> ctx
    attn_kernel<<<dim3(S_ / AM, B_ * NH_), 256, ATTN_SMEM_BYTES>>>(qkv, alibi, ctx);

    // 3) split ctx, dense projection + bias + residual
    split_rows<<<(M_ * H_ / 4 + 255) / 256, 256>>>(ctx, Ch, Cl, M_ * H_ / 4);
    mma_gemm<true><<<dim3(M_ / 128, H_ / 128), 256, GSM_TOTAL>>>(
        Ch, Cl, Bdh, Bdl, bd, residual, out, H_, H_);
}

// round 5
// speedup vs baseline: 3.1006x; 1.2394x over previous
#include <cuda_runtime.h>
#include <cuda_bf16.h>
#include <stdint.h>
#include <math.h>

// Problem constants
#define B_    2
#define S_    1024
#define H_    4096
#define NH_   32
#define HD_   128
#define M_    2048
#define NQKV_ 12288

// ---------------- device scratch (no runtime allocation) ----------------
__device__ float g_qkv[(size_t)M_ * NQKV_];
__device__ __nv_bfloat16 g_Ah[(size_t)M_ * H_];
__device__ __nv_bfloat16 g_Al[(size_t)M_ * H_];
__device__ __nv_bfloat16 g_Bqh[(size_t)NQKV_ * H_];
__device__ __nv_bfloat16 g_Bql[(size_t)NQKV_ * H_];
__device__ __nv_bfloat16 g_Bdh[(size_t)H_ * H_];
__device__ __nv_bfloat16 g_Bdl[(size_t)H_ * H_];
__device__ __nv_bfloat16 g_Ch[(size_t)M_ * H_];
__device__ __nv_bfloat16 g_Cl[(size_t)M_ * H_];

// ---------------- PTX helpers (portable, non-'a' features only) ----------------
__device__ __forceinline__ uint32_t smem_u32(const void* p) {
    uint32_t a;
    asm("{ .reg .u64 t; cvta.to.shared.u64 t, %1; cvt.u32.u64 %0, t; }" : "=r"(a) : "l"(p));
    return a;
}
__device__ __forceinline__ void cp_async16(uint32_t dst_smem, const void* src) {
    asm volatile("cp.async.cg.shared.global [%0], [%1], 16;"
                 :: "r"(dst_smem), "l"(src) : "memory");
}
__device__ __forceinline__ void cp_commit() {
    asm volatile("cp.async.commit_group;" ::: "memory");
}
__device__ __forceinline__ void cp_wait1() {
    asm volatile("cp.async.wait_group 1;" ::: "memory");
}
__device__ __forceinline__ void ldsm4(uint32_t* r, uint32_t addr) {
    asm volatile("ldmatrix.sync.aligned.m8n8.x4.shared.b16 {%0,%1,%2,%3}, [%4];"
                 : "=r"(r[0]), "=r"(r[1]), "=r"(r[2]), "=r"(r[3]) : "r"(addr));
}
__device__ __forceinline__ void ldsm4t(uint32_t* r, uint32_t addr) {
    asm volatile("ldmatrix.sync.aligned.m8n8.x4.trans.shared.b16 {%0,%1,%2,%3}, [%4];"
                 : "=r"(r[0]), "=r"(r[1]), "=r"(r[2]), "=r"(r[3]) : "r"(addr));
}
__device__ __forceinline__ void mma_bf16(float* d, const uint32_t* a, const uint32_t* b) {
    asm volatile(
        "mma.sync.aligned.m16n8k16.row.col.f32.bf16.bf16.f32 "
        "{%0,%1,%2,%3}, {%4,%5,%6,%7}, {%8,%9}, {%0,%1,%2,%3};"
        : "+f"(d[0]), "+f"(d[1]), "+f"(d[2]), "+f"(d[3])
        : "r"(a[0]), "r"(a[1]), "r"(a[2]), "r"(a[3]), "r"(b[0]), "r"(b[1]));
}
// pack two floats to bf16x2: low half = lo, high half = hi
__device__ __forceinline__ uint32_t pack_bf16(float lo, float hi) {
    uint32_t r;
    asm("cvt.rn.bf16x2.f32 %0, %1, %2;" : "=r"(r) : "f"(hi), "f"(lo));
    return r;
}
__device__ __forceinline__ float2 unpack_bf16(uint32_t v) {
    __nv_bfloat162 h = *reinterpret_cast<__nv_bfloat162*>(&v);
    return __bfloat1622float2(h);
}

// ---------------- split helpers ----------------
__device__ __forceinline__ void split1(float f, __nv_bfloat16& h, __nv_bfloat16& l) {
    h = __float2bfloat16(f);
    l = __float2bfloat16(f - __bfloat162float(h));
}

__global__ __launch_bounds__(256)
void split_rows(const float* __restrict__ in, __nv_bfloat16* __restrict__ hi,
                __nv_bfloat16* __restrict__ lo, int n4)
{
    int i = blockIdx.x * 256 + threadIdx.x;
    if (i >= n4) return;
    float4 v = ((const float4*)in)[i];
    __nv_bfloat16 h0, h1, h2, h3, l0, l1, l2, l3;
    split1(v.x, h0, l0); split1(v.y, h1, l1); split1(v.z, h2, l2); split1(v.w, h3, l3);
    __nv_bfloat162* hp = (__nv_bfloat162*)hi;
    __nv_bfloat162* lp = (__nv_bfloat162*)lo;
    hp[2 * i]     = __nv_bfloat162(h0, h1);
    hp[2 * i + 1] = __nv_bfloat162(h2, h3);
    lp[2 * i]     = __nv_bfloat162(l0, l1);
    lp[2 * i + 1] = __nv_bfloat162(l2, l3);
}

// W [K][N] fp32 -> B [N][K] bf16 hi/lo (transpose + split)
__global__ __launch_bounds__(256)
void split_transpose(const float* __restrict__ W, __nv_bfloat16* __restrict__ Bh,
                     __nv_bfloat16* __restrict__ Bl, int K, int N)
{
    __shared__ float ts[32][33];
    int n0 = blockIdx.x * 32, k0 = blockIdx.y * 32;
    int tx = threadIdx.x, ty = threadIdx.y;  // (32, 8)
#pragma unroll
    for (int i = 0; i < 4; i++)
        ts[ty + i * 8][tx] = W[(size_t)(k0 + ty + i * 8) * N + n0 + tx];
    __syncthreads();
#pragma unroll
    for (int i = 0; i < 4; i++) {
        float f = ts[tx][ty + i * 8];
        __nv_bfloat16 h, l;
        split1(f, h, l);
        size_t o = (size_t)(n0 + ty + i * 8) * K + k0 + tx;
        Bh[o] = h;
        Bl[o] = l;
    }
}

// ============================================================
// mma.sync split-bf16 GEMM (unchanged from round 4)
// ============================================================
#define STAGE_BYTES 32768
#define GSTAGES 3
#define GSM_TOTAL (GSTAGES * STAGE_BYTES)

template<bool RES>
__global__ __launch_bounds__(256, 1)
void mma_gemm(const __nv_bfloat16* __restrict__ Ah, const __nv_bfloat16* __restrict__ Al,
              const __nv_bfloat16* __restrict__ Bh, const __nv_bfloat16* __restrict__ Bl,
              const float* __restrict__ bias, const float* __restrict__ res,
              float* __restrict__ C, int N, int K)
{
    extern __shared__ __align__(1024) char smem[];
    const uint32_t sb = smem_u32(smem);
    const int tid  = threadIdx.x;
    const int lane = tid & 31;
    const int warp = tid >> 5;
    const int wm = warp >> 2;
    const int wn = warp & 3;
    const int row0 = blockIdx.x * 128;
    const int col0 = blockIdx.y * 128;

    const int aRow = wm * 64 + (lane & 15);
    const uint32_t aSw = (uint32_t)((aRow >> 1) & 3);
    const uint32_t aCH = (uint32_t)(lane >> 4);
    const int bRow = wn * 32 + (((lane >> 4) & 1) << 3) + (lane & 7);
    const uint32_t bSw = (uint32_t)((bRow >> 1) & 3);
    const uint32_t bCH = (uint32_t)((lane >> 3) & 1);

    float acc[4][4][4];
#pragma unroll
    for (int mt = 0; mt < 4; mt++)
#pragma unroll
        for (int nt = 0; nt < 4; nt++)
#pragma unroll
            for (int e = 0; e < 4; e++) acc[mt][nt][e] = 0.f;

    const int ldRowA = row0 + (tid >> 2);
    const int ldRowB = col0 + (tid >> 2);
    const int ldC    = tid & 3;
    const uint32_t ldSw = ((uint32_t)(tid >> 2) * 64) ^
                          (((uint32_t)ldC ^ (((uint32_t)(tid >> 2) >> 1) & 3)) << 4);
    const uint32_t ldSw2 = (((uint32_t)(tid >> 2) + 64) * 64) ^
                           (((uint32_t)ldC ^ ((((uint32_t)(tid >> 2) + 64) >> 1) & 3)) << 4);

    const int NK = K / 32;

    auto load_stage = [&](int s, int k0) {
        uint32_t base = sb + (uint32_t)s * STAGE_BYTES;
        const __nv_bfloat16* gA0 = Ah + (size_t)ldRowA * K + k0 + ldC * 8;
        const __nv_bfloat16* gA1 = Al + (size_t)ldRowA * K + k0 + ldC * 8;
        const __nv_bfloat16* gB0 = Bh + (size_t)ldRowB * K + k0 + ldC * 8;
        const __nv_bfloat16* gB1 = Bl + (size_t)ldRowB * K + k0 + ldC * 8;
        const size_t off64 = (size_t)64 * K;
        cp_async16(base + ldSw,                gA0);
        cp_async16(base + ldSw2,               gA0 + off64);
        cp_async16(base + 8192  + ldSw,        gA1);
        cp_async16(base + 8192  + ldSw2,       gA1 + off64);
        cp_async16(base + 16384 + ldSw,        gB0);
        cp_async16(base + 16384 + ldSw2,       gB0 + off64);
        cp_async16(base + 24576 + ldSw,        gB1);
        cp_async16(base + 24576 + ldSw2,       gB1 + off64);
    };

    load_stage(0, 0);  cp_commit();
    load_stage(1, 32); cp_commit();

    int st = 0;
    for (int kt = 0; kt < NK; kt++) {
        cp_wait1();
        __syncthreads();

        uint32_t base = sb + (uint32_t)st * STAGE_BYTES;
        uint32_t aHiB = base +         (uint32_t)aRow * 64;
        uint32_t aLoB = aHiB + 8192;
        uint32_t bHiB = base + 16384 + (uint32_t)bRow * 64;
        uint32_t bLoB = bHiB + 8192;

#pragma unroll
        for (int k = 0; k < 2; k++) {
            const uint32_t ka = ((2u * k + aCH) ^ aSw) << 4;
            const uint32_t kb = ((2u * k + bCH) ^ bSw) << 4;
            uint32_t ahi[4][4], bhi[2][4];
#pragma unroll
            for (int mt = 0; mt < 4; mt++) ldsm4(ahi[mt], aHiB + mt * 1024 + ka);
#pragma unroll
            for (int p = 0; p < 2; p++)    ldsm4(bhi[p], bHiB + p * 1024 + kb);
#pragma unroll
            for (int mt = 0; mt < 4; mt++)
#pragma unroll
                for (int nt = 0; nt < 4; nt++)
                    mma_bf16(acc[mt][nt], ahi[mt], &bhi[nt >> 1][(nt & 1) * 2]);
            uint32_t blo[2][4];
#pragma unroll
            for (int p = 0; p < 2; p++) ldsm4(blo[p], bLoB + p * 1024 + kb);
#pragma unroll
            for (int mt = 0; mt < 4; mt++)
#pragma unroll
                for (int nt = 0; nt < 4; nt++)
                    mma_bf16(acc[mt][nt], ahi[mt], &blo[nt >> 1][(nt & 1) * 2]);
            uint32_t alo[4][4];
#pragma unroll
            for (int mt = 0; mt < 4; mt++) ldsm4(alo[mt], aLoB + mt * 1024 + ka);
#pragma unroll
            for (int mt = 0; mt < 4; mt++)
#pragma unroll
                for (int nt = 0; nt < 4; nt++)
                    mma_bf16(acc[mt][nt], alo[mt], &bhi[nt >> 1][(nt & 1) * 2]);
        }

        if (kt + 2 < NK) load_stage((st + 2) % GSTAGES, (kt + 2) * 32);
        cp_commit();
        st = (st + 1) % GSTAGES;
    }

    const int g  = lane >> 2;
    const int i4 = lane & 3;
#pragma unroll
    for (int mt = 0; mt < 4; mt++) {
        int r = row0 + wm * 64 + mt * 16 + g;
#pragma unroll
        for (int nt = 0; nt < 4; nt++) {
            int c = col0 + wn * 32 + nt * 8 + i4 * 2;
            float2 bv = *(const float2*)(bias + c);
            size_t o0 = (size_t)r * N + c;
            size_t o1 = (size_t)(r + 8) * N + c;
            float2 v0, v1;
            v0.x = acc[mt][nt][0] + bv.x; v0.y = acc[mt][nt][1] + bv.y;
            v1.x = acc[mt][nt][2] + bv.x; v1.y = acc[mt][nt][3] + bv.y;
            if (RES) {
                float2 r0 = *(const float2*)(res + o0);
                float2 r1 = *(const float2*)(res + o1);
                v0.x += r0.x; v0.y += r0.y;
                v1.x += r1.x; v1.y += r1.y;
            }
            *(float2*)(C + o0) = v0;
            *(float2*)(C + o1) = v1;
        }
    }
}

// ============================================================
// FA2-style attention on mma.sync, split-bf16 3-term.
// CTA: q-tile 128 (8 warps x m16), kv-tile 64.
// smem bf16 tiles: rows of 256B (128 bf16), 16B-chunk swizzle:
//   addr(r, chunk) = r*256 + ((chunk ^ (r&7)) << 4)
// Writes ctx directly as bf16 hi/lo (feeds dense GEMM).
// ============================================================
#define AQ_OFF   0u        // Qhi 32KB
#define AQL_OFF  32768u    // Qlo 32KB
#define AK_OFF   65536u    // Khi 16KB
#define AKL_OFF  81920u    // Klo 16KB
#define AV_OFF   98304u    // Vhi 16KB
#define AVL_OFF  114688u   // Vlo 16KB
#define AAL_OFF  131072u   // alibi 64 floats
#define ATTN_SMEM (131072 + 256)

__device__ __forceinline__ void store_split8(uint32_t baseH, uint32_t baseL,
                                             int r, int d, float4 v)
{
    uint32_t h01 = pack_bf16(v.x, v.y);
    uint32_t h23 = pack_bf16(v.z, v.w);
    float2 f01 = unpack_bf16(h01);
    float2 f23 = unpack_bf16(h23);
    uint32_t l01 = pack_bf16(v.x - f01.x, v.y - f01.y);
    uint32_t l23 = pack_bf16(v.z - f23.x, v.w - f23.y);
    uint32_t off = (uint32_t)r * 256 + ((((uint32_t)d >> 3) ^ ((uint32_t)r & 7)) << 4)
                 + (((uint32_t)d & 4) << 1);
    asm volatile("st.shared.v2.b32 [%0], {%1,%2};" :: "r"(baseH + off), "r"(h01), "r"(h23));
    asm volatile("st.shared.v2.b32 [%0], {%1,%2};" :: "r"(baseL + off), "r"(l01), "r"(l23));
}

__global__ __launch_bounds__(256, 1)
void attn_mma(const float* __restrict__ qkv, const float* __restrict__ alibi,
              __nv_bfloat16* __restrict__ Ch, __nv_bfloat16* __restrict__ Cl)
{
    extern __shared__ __align__(1024) char sm[];
    const uint32_t sb = smem_u32(sm);
    const uint32_t Qh = sb + AQ_OFF,  Ql = sb + AQL_OFF;
    const uint32_t Kh = sb + AK_OFF,  Kl = sb + AKL_OFF;
    const uint32_t Vh = sb + AV_OFF,  Vl = sb + AVL_OFF;
    float* al_s = (float*)(sm + AAL_OFF);

    const int qt   = blockIdx.x;
    const int bh   = blockIdx.y;
    const int b    = bh >> 5;
    const int h    = bh & 31;
    const int tid  = threadIdx.x;
    const int lane = tid & 31;
    const int warp = tid >> 5;

    const size_t rowbase = (size_t)b * S_;
    const int qcol = h * 384;
    const float* al = alibi + (size_t)bh * S_;
    const float inv = 0.08838834764831845f;

    // ---- load Q tile [128][128] fp32 -> split -> smem ----
#pragma unroll 4
    for (int it = 0; it < 16; it++) {
        int r = it * 8 + warp;
        int d = lane * 4;
        float4 v = *(const float4*)(qkv + (rowbase + qt * 128 + r) * NQKV_ + qcol + d);
        store_split8(Qh, Ql, r, d, v);
    }

    // per-thread fragment addressing
    const int aRow = warp * 16 + (lane & 15);            // Q rows for ldsm (within tile)
    const uint32_t aChH = (uint32_t)(lane >> 4);         // k-chunk half for A
    const int bRowBase = (((lane >> 4) & 1) << 3) + (lane & 7);  // + p*16
    const uint32_t bChH = (uint32_t)((lane >> 3) & 1);
    // V trans-ldsm lane mapping
    const int vTok = (lane & 7) + (lane & 8);            // + ks*16
    const int vD   = (lane >> 4) << 3;                   // + nt16*16

    const int g  = lane >> 2;
    const int c2 = (lane & 3) * 2;
    const int qg0 = qt * 128 + warp * 16 + g;            // global q row (and +8)

    float O[16][4];
#pragma unroll
    for (int n = 0; n < 16; n++)
#pragma unroll
        for (int e = 0; e < 4; e++) O[n][e] = 0.f;
    float m0 = -1e30f, m1 = -1e30f, l0 = 0.f, l1 = 0.f;

    const int jmax = 2 * qt + 1;
    for (int j = 0; j <= jmax; j++) {
        __syncthreads();
        // ---- load K,V tiles [64][128] fp32 -> split -> smem; alibi -> al_s ----
#pragma unroll 4
        for (int it = 0; it < 8; it++) {
            int r = it * 8 + warp;
            int d = lane * 4;
            const float* src = qkv + (rowbase + j * 64 + r) * NQKV_ + qcol + d;
            float4 kv4 = *(const float4*)(src + 128);
            float4 vv4 = *(const float4*)(src + 256);
            store_split8(Kh, Kl, r, d, kv4);
            store_split8(Vh, Vl, r, d, vv4);
        }
        if (tid < 16) ((float4*)al_s)[tid] = *(const float4*)(al + j * 64 + tid * 4);
        __syncthreads();

        // ---- S = Q K^T (3-term split), m16 x n64 per warp ----
        float S[8][4];
#pragma unroll
        for (int n = 0; n < 8; n++)
#pragma unroll
            for (int e = 0; e < 4; e++) S[n][e] = 0.f;

#pragma unroll
        for (int ks = 0; ks < 8; ks++) {
            uint32_t aOff = (uint32_t)aRow * 256 +
                (((2u * ks + aChH) ^ ((uint32_t)aRow & 7)) << 4);
            uint32_t ahi[4], alo[4];
            ldsm4(ahi, Qh + aOff);
            ldsm4(alo, Ql + aOff);
#pragma unroll
            for (int p = 0; p < 4; p++) {
                int bRow = p * 16 + bRowBase;
                uint32_t bOff = (uint32_t)bRow * 256 +
                    (((2u * ks + bChH) ^ ((uint32_t)bRow & 7)) << 4);
                uint32_t bhi[4], blo[4];
                ldsm4(bhi, Kh + bOff);
                ldsm4(blo, Kl + bOff);
#pragma unroll
                for (int q2 = 0; q2 < 2; q2++) {
                    int nt = p * 2 + q2;
                    mma_bf16(S[nt], ahi, &bhi[q2 * 2]);
                    mma_bf16(S[nt], ahi, &blo[q2 * 2]);
                    mma_bf16(S[nt], alo, &bhi[q2 * 2]);
                }
            }
        }

        // ---- scale + alibi + causal mask ----
        const bool diag = (j * 64 + 63 > qt * 128 + warp * 16);
#pragma unroll
        for (int nt = 0; nt < 8; nt++) {
            float a0 = al_s[nt * 8 + c2];
            float a1 = al_s[nt * 8 + c2 + 1];
            S[nt][0] = S[nt][0] * inv + a0;
            S[nt][1] = S[nt][1] * inv + a1;
            S[nt][2] = S[nt][2] * inv + a0;
            S[nt][3] = S[nt][3] * inv + a1;
            if (diag) {
                int kg = j * 64 + nt * 8 + c2;
                if (kg     > qg0)     S[nt][0] = -1e30f;
                if (kg + 1 > qg0)     S[nt][1] = -1e30f;
                if (kg     > qg0 + 8) S[nt][2] = -1e30f;
                if (kg + 1 > qg0 + 8) S[nt][3] = -1e30f;
            }
        }

        // ---- online softmax (rows g, g+8; reduce across 4-lane quads) ----
        float mx0 = -1e30f, mx1 = -1e30f;
#pragma unroll
        for (int nt = 0; nt < 8; nt++) {
            mx0 = fmaxf(mx0, fmaxf(S[nt][0], S[nt][1]));
            mx1 = fmaxf(mx1, fmaxf(S[nt][2], S[nt][3]));
        }
        mx0 = fmaxf(mx0, __shfl_xor_sync(0xffffffffu, mx0, 1));
        mx0 = fmaxf(mx0, __shfl_xor_sync(0xffffffffu, mx0, 2));
        mx1 = fmaxf(mx1, __shfl_xor_sync(0xffffffffu, mx1, 1));
        mx1 = fmaxf(mx1, __shfl_xor_sync(0xffffffffu, mx1, 2));
        float mn0 = fmaxf(m0, mx0), mn1 = fmaxf(m1, mx1);
        float sf0 = __expf(m0 - mn0), sf1 = __expf(m1 - mn1);
        float sum0 = 0.f, sum1 = 0.f;
#pragma unroll
        for (int nt = 0; nt < 8; nt++) {
            S[nt][0] = __expf(S[nt][0] - mn0); sum0 += S[nt][0];
            S[nt][1] = __expf(S[nt][1] - mn0); sum0 += S[nt][1];
            S[nt][2] = __expf(S[nt][2] - mn1); sum1 += S[nt][2];
            S[nt][3] = __expf(S[nt][3] - mn1); sum1 += S[nt][3];
        }
        sum0 += __shfl_xor_sync(0xffffffffu, sum0, 1);
        sum0 += __shfl_xor_sync(0xffffffffu, sum0, 2);
        sum1 += __shfl_xor_sync(0xffffffffu, sum1, 1);
        sum1 += __shfl_xor_sync(0xffffffffu, sum1, 2);
        l0 = l0 * sf0 + sum0; m0 = mn0;
        l1 = l1 * sf1 + sum1; m1 = mn1;
#pragma unroll
        for (int n = 0; n < 16; n++) {
            O[n][0] *= sf0; O[n][1] *= sf0;
            O[n][2] *= sf1; O[n][3] *= sf1;
        }

        // ---- O += P V (P from S-fragments, 3-term split; V via ldsm.trans) ----
#pragma unroll
        for (int ks = 0; ks < 4; ks++) {
            uint32_t pa_hi[4], pa_lo[4];
            {
                float x0 = S[2 * ks][0],     x1 = S[2 * ks][1];
                float x2 = S[2 * ks][2],     x3 = S[2 * ks][3];
                float y0 = S[2 * ks + 1][0], y1 = S[2 * ks + 1][1];
                float y2 = S[2 * ks + 1][2], y3 = S[2 * ks + 1][3];
                pa_hi[0] = pack_bf16(x0, x1);
                pa_hi[1] = pack_bf16(x2, x3);
                pa_hi[2] = pack_bf16(y0, y1);
                pa_hi[3] = pack_bf16(y2, y3);
                float2 u;
                u = unpack_bf16(pa_hi[0]); pa_lo[0] = pack_bf16(x0 - u.x, x1 - u.y);
                u = unpack_bf16(pa_hi[1]); pa_lo[1] = pack_bf16(x2 - u.x, x3 - u.y);
                u = unpack_bf16(pa_hi[2]); pa_lo[2] = pack_bf16(y0 - u.x, y1 - u.y);
                u = unpack_bf16(pa_hi[3]); pa_lo[3] = pack_bf16(y2 - u.x, y3 - u.y);
            }
            int tok = ks * 16 + vTok;
            uint32_t tRow = (uint32_t)tok * 256;
            uint32_t tSw  = (uint32_t)tok & 7;
#pragma unroll
            for (int nt16 = 0; nt16 < 8; nt16++) {
                int d = nt16 * 16 + vD;
                uint32_t vOff = tRow + ((((uint32_t)d >> 3) ^ tSw) << 4);
                uint32_t bvh[4], bvl[4];
                ldsm4t(bvh, Vh + vOff);
                ldsm4t(bvl, Vl + vOff);
                mma_bf16(O[nt16 * 2],     pa_hi, &bvh[0]);
                mma_bf16(O[nt16 * 2 + 1], pa_hi, &bvh[2]);
                mma_bf16(O[nt16 * 2],     pa_hi, &bvl[0]);
                mma_bf16(O[nt16 * 2 + 1], pa_hi, &bvl[2]);
                mma_bf16(O[nt16 * 2],     pa_lo, &bvh[0]);
                mma_bf16(O[nt16 * 2 + 1], pa_lo, &bvh[2]);
            }
        }
    }

    // ---- epilogue: ctx = O / l, written as bf16 hi/lo ----
    float il0 = 1.f / l0, il1 = 1.f / l1;
    size_t r0 = rowbase + qt * 128 + warp * 16 + g;
    size_t r1 = r0 + 8;
#pragma unroll
    for (int n = 0; n < 16; n++) {
        int col = h * 128 + n * 8 + c2;
        float o00 = O[n][0] * il0, o01 = O[n][1] * il0;
        float o10 = O[n][2] * il1, o11 = O[n][3] * il1;
        uint32_t h0 = pack_bf16(o00, o01);
        uint32_t h1 = pack_bf16(o10, o11);
        float2 u0 = unpack_bf16(h0);
        float2 u1 = unpack_bf16(h1);
        uint32_t lo0 = pack_bf16(o00 - u0.x, o01 - u0.y);
        uint32_t lo1 = pack_bf16(o10 - u1.x, o11 - u1.y);
        *(uint32_t*)(Ch + r0 * H_ + col) = h0;
        *(uint32_t*)(Cl + r0 * H_ + col) = lo0;
        *(uint32_t*)(Ch + r1 * H_ + col) = h1;
        *(uint32_t*)(Cl + r1 * H_ + col) = lo1;
    }
}

// ============================================================
// Launch
// ============================================================
extern "C" void kernel_launch(void* const* d_in, const int* in_sizes, int n_in,
                              void* d_out, int out_size)
{
    const float* hidden   = (const float*)d_in[0];
    const float* residual = (const float*)d_in[1];
    const float* alibi    = (const float*)d_in[2];
    const float* Wqkv     = (const float*)d_in[4];
    const float* bqkv     = (const float*)d_in[5];
    const float* Wd       = (const float*)d_in[6];
    const float* bd       = (const float*)d_in[7];
    float* out = (float*)d_out;

    void* p;
    cudaGetSymbolAddress(&p, g_qkv); float* qkv = (float*)p;
    cudaGetSymbolAddress(&p, g_Ah);  __nv_bfloat16* Ah  = (__nv_bfloat16*)p;
    cudaGetSymbolAddress(&p, g_Al);  __nv_bfloat16* Al  = (__nv_bfloat16*)p;
    cudaGetSymbolAddress(&p, g_Bqh); __nv_bfloat16* Bqh = (__nv_bfloat16*)p;
    cudaGetSymbolAddress(&p, g_Bql); __nv_bfloat16* Bql = (__nv_bfloat16*)p;
    cudaGetSymbolAddress(&p, g_Bdh); __nv_bfloat16* Bdh = (__nv_bfloat16*)p;
    cudaGetSymbolAddress(&p, g_Bdl); __nv_bfloat16* Bdl = (__nv_bfloat16*)p;
    cudaGetSymbolAddress(&p, g_Ch);  __nv_bfloat16* Ch  = (__nv_bfloat16*)p;
    cudaGetSymbolAddress(&p, g_Cl);  __nv_bfloat16* Cl  = (__nv_bfloat16*)p;

    cudaFuncSetAttribute(attn_mma, cudaFuncAttributeMaxDynamicSharedMemorySize, ATTN_SMEM);
    cudaFuncSetAttribute(mma_gemm<false>, cudaFuncAttributeMaxDynamicSharedMemorySize, GSM_TOTAL);
    cudaFuncSetAttribute(mma_gemm<true>,  cudaFuncAttributeMaxDynamicSharedMemorySize, GSM_TOTAL);

    // 0) split inputs to bf16 hi/lo
    split_rows<<<(M_ * H_ / 4 + 255) / 256, 256>>>(hidden, Ah, Al, M_ * H_ / 4);
    split_transpose<<<dim3(NQKV_ / 32, H_ / 32), dim3(32, 8)>>>(Wqkv, Bqh, Bql, H_, NQKV_);
    split_transpose<<<dim3(H_ / 32, H_ / 32), dim3(32, 8)>>>(Wd, Bdh, Bdl, H_, H_);

    // 1) QKV projection
    mma_gemm<false><<<dim3(M_ / 128, NQKV_ / 128), 256, GSM_TOTAL>>>(
        Ah, Al, Bqh, Bql, bqkv, nullptr, qkv, NQKV_, H_);

    // 2) attention -> ctx (bf16 hi/lo, directly consumable by dense GEMM)
    attn_mma<<<dim3(S_ / 128, B_ * NH_), 256, ATTN_SMEM>>>(qkv, alibi, Ch, Cl);

    // 3) dense projection + bias + residual
    mma_gemm<true><<<dim3(M_ / 128, H_ / 128), 256, GSM_TOTAL>>>(
        Ch, Cl, Bdh, Bdl, bd, residual, out, H_, H_);
}

// round 6
// speedup vs baseline: 3.4189x; 1.1027x over previous
#include <cuda_runtime.h>
#include <cuda_bf16.h>
#include <stdint.h>
#include <math.h>

// Problem constants
#define B_    2
#define S_    1024
#define H_    4096
#define NH_   32
#define HD_   128
#define M_    2048
#define NQKV_ 12288

// ---------------- device scratch (no runtime allocation) ----------------
__device__ float g_qkv[(size_t)M_ * NQKV_];
__device__ __nv_bfloat16 g_Ah[(size_t)M_ * H_];
__device__ __nv_bfloat16 g_Al[(size_t)M_ * H_];
__device__ __nv_bfloat16 g_Bqh[(size_t)NQKV_ * H_];
__device__ __nv_bfloat16 g_Bql[(size_t)NQKV_ * H_];
__device__ __nv_bfloat16 g_Bdh[(size_t)H_ * H_];
__device__ __nv_bfloat16 g_Bdl[(size_t)H_ * H_];
__device__ __nv_bfloat16 g_Ch[(size_t)M_ * H_];
__device__ __nv_bfloat16 g_Cl[(size_t)M_ * H_];

// ---------------- PTX helpers (portable, non-'a' features only) ----------------
__device__ __forceinline__ uint32_t smem_u32(const void* p) {
    uint32_t a;
    asm("{ .reg .u64 t; cvta.to.shared.u64 t, %1; cvt.u32.u64 %0, t; }" : "=r"(a) : "l"(p));
    return a;
}
__device__ __forceinline__ void cp_async16(uint32_t dst_smem, const void* src) {
    asm volatile("cp.async.cg.shared.global [%0], [%1], 16;"
                 :: "r"(dst_smem), "l"(src) : "memory");
}
__device__ __forceinline__ void cp_commit() {
    asm volatile("cp.async.commit_group;" ::: "memory");
}
__device__ __forceinline__ void cp_wait1() {
    asm volatile("cp.async.wait_group 1;" ::: "memory");
}
__device__ __forceinline__ void ldsm4(uint32_t* r, uint32_t addr) {
    asm volatile("ldmatrix.sync.aligned.m8n8.x4.shared.b16 {%0,%1,%2,%3}, [%4];"
                 : "=r"(r[0]), "=r"(r[1]), "=r"(r[2]), "=r"(r[3]) : "r"(addr));
}
__device__ __forceinline__ void ldsm4t(uint32_t* r, uint32_t addr) {
    asm volatile("ldmatrix.sync.aligned.m8n8.x4.trans.shared.b16 {%0,%1,%2,%3}, [%4];"
                 : "=r"(r[0]), "=r"(r[1]), "=r"(r[2]), "=r"(r[3]) : "r"(addr));
}
__device__ __forceinline__ void mma_bf16(float* d, const uint32_t* a, const uint32_t* b) {
    asm volatile(
        "mma.sync.aligned.m16n8k16.row.col.f32.bf16.bf16.f32 "
        "{%0,%1,%2,%3}, {%4,%5,%6,%7}, {%8,%9}, {%0,%1,%2,%3};"
        : "+f"(d[0]), "+f"(d[1]), "+f"(d[2]), "+f"(d[3])
        : "r"(a[0]), "r"(a[1]), "r"(a[2]), "r"(a[3]), "r"(b[0]), "r"(b[1]));
}
// pack two floats to bf16x2: low half = lo, high half = hi
__device__ __forceinline__ uint32_t pack_bf16(float lo, float hi) {
    uint32_t r;
    asm("cvt.rn.bf16x2.f32 %0, %1, %2;" : "=r"(r) : "f"(hi), "f"(lo));
    return r;
}
__device__ __forceinline__ float2 unpack_bf16(uint32_t v) {
    __nv_bfloat162 h = *reinterpret_cast<__nv_bfloat162*>(&v);
    return __bfloat1622float2(h);
}

// ---------------- split helpers ----------------
__device__ __forceinline__ void split1(float f, __nv_bfloat16& h, __nv_bfloat16& l) {
    h = __float2bfloat16(f);
    l = __float2bfloat16(f - __bfloat162float(h));
}

__global__ __launch_bounds__(256)
void split_rows(const float* __restrict__ in, __nv_bfloat16* __restrict__ hi,
                __nv_bfloat16* __restrict__ lo, int n4)
{
    int i = blockIdx.x * 256 + threadIdx.x;
    if (i >= n4) return;
    float4 v = ((const float4*)in)[i];
    __nv_bfloat16 h0, h1, h2, h3, l0, l1, l2, l3;
    split1(v.x, h0, l0); split1(v.y, h1, l1); split1(v.z, h2, l2); split1(v.w, h3, l3);
    __nv_bfloat162* hp = (__nv_bfloat162*)hi;
    __nv_bfloat162* lp = (__nv_bfloat162*)lo;
    hp[2 * i]     = __nv_bfloat162(h0, h1);
    hp[2 * i + 1] = __nv_bfloat162(h2, h3);
    lp[2 * i]     = __nv_bfloat162(l0, l1);
    lp[2 * i + 1] = __nv_bfloat162(l2, l3);
}

// W [K][N] fp32 -> B [N][K] bf16 hi/lo (transpose + split)
__global__ __launch_bounds__(256)
void split_transpose(const float* __restrict__ W, __nv_bfloat16* __restrict__ Bh,
                     __nv_bfloat16* __restrict__ Bl, int K, int N)
{
    __shared__ float ts[32][33];
    int n0 = blockIdx.x * 32, k0 = blockIdx.y * 32;
    int tx = threadIdx.x, ty = threadIdx.y;  // (32, 8)
#pragma unroll
    for (int i = 0; i < 4; i++)
        ts[ty + i * 8][tx] = W[(size_t)(k0 + ty + i * 8) * N + n0 + tx];
    __syncthreads();
#pragma unroll
    for (int i = 0; i < 4; i++) {
        float f = ts[tx][ty + i * 8];
        __nv_bfloat16 h, l;
        split1(f, h, l);
        size_t o = (size_t)(n0 + ty + i * 8) * K + k0 + tx;
        Bh[o] = h;
        Bl[o] = l;
    }
}

// ============================================================
// mma.sync split-bf16 GEMM. 128x128 CTA tile, BK=32, 8 warps,
// 3-stage cp.async. Restructured for <=128 regs -> 2 CTAs/SM.
// ============================================================
#define STAGE_BYTES 32768
#define GSTAGES 3
#define GSM_TOTAL (GSTAGES * STAGE_BYTES)

template<bool RES>
__global__ __launch_bounds__(256, 2)
void mma_gemm(const __nv_bfloat16* __restrict__ Ah, const __nv_bfloat16* __restrict__ Al,
              const __nv_bfloat16* __restrict__ Bh, const __nv_bfloat16* __restrict__ Bl,
              const float* __restrict__ bias, const float* __restrict__ res,
              float* __restrict__ C, int N, int K)
{
    extern __shared__ __align__(1024) char smem[];
    const uint32_t sb = smem_u32(smem);
    const int tid  = threadIdx.x;
    const int lane = tid & 31;
    const int warp = tid >> 5;
    const int wm = warp >> 2;
    const int wn = warp & 3;
    const int row0 = blockIdx.x * 128;
    const int col0 = blockIdx.y * 128;

    const int aRow = wm * 64 + (lane & 15);
    const uint32_t aSw = (uint32_t)((aRow >> 1) & 3);
    const uint32_t aCH = (uint32_t)(lane >> 4);
    const int bRow = wn * 32 + (((lane >> 4) & 1) << 3) + (lane & 7);
    const uint32_t bSw = (uint32_t)((bRow >> 1) & 3);
    const uint32_t bCH = (uint32_t)((lane >> 3) & 1);

    float acc[4][4][4];
#pragma unroll
    for (int mt = 0; mt < 4; mt++)
#pragma unroll
        for (int nt = 0; nt < 4; nt++)
#pragma unroll
            for (int e = 0; e < 4; e++) acc[mt][nt][e] = 0.f;

    const int ldRowA = row0 + (tid >> 2);
    const int ldRowB = col0 + (tid >> 2);
    const int ldC    = tid & 3;
    const uint32_t ldSw = ((uint32_t)(tid >> 2) * 64) ^
                          (((uint32_t)ldC ^ (((uint32_t)(tid >> 2) >> 1) & 3)) << 4);
    const uint32_t ldSw2 = (((uint32_t)(tid >> 2) + 64) * 64) ^
                           (((uint32_t)ldC ^ ((((uint32_t)(tid >> 2) + 64) >> 1) & 3)) << 4);

    const int NK = K / 32;

    auto load_stage = [&](int s, int k0) {
        uint32_t base = sb + (uint32_t)s * STAGE_BYTES;
        const __nv_bfloat16* gA0 = Ah + (size_t)ldRowA * K + k0 + ldC * 8;
        const __nv_bfloat16* gA1 = Al + (size_t)ldRowA * K + k0 + ldC * 8;
        const __nv_bfloat16* gB0 = Bh + (size_t)ldRowB * K + k0 + ldC * 8;
        const __nv_bfloat16* gB1 = Bl + (size_t)ldRowB * K + k0 + ldC * 8;
        const size_t off64 = (size_t)64 * K;
        cp_async16(base + ldSw,                gA0);
        cp_async16(base + ldSw2,               gA0 + off64);
        cp_async16(base + 8192  + ldSw,        gA1);
        cp_async16(base + 8192  + ldSw2,       gA1 + off64);
        cp_async16(base + 16384 + ldSw,        gB0);
        cp_async16(base + 16384 + ldSw2,       gB0 + off64);
        cp_async16(base + 24576 + ldSw,        gB1);
        cp_async16(base + 24576 + ldSw2,       gB1 + off64);
    };

    load_stage(0, 0);  cp_commit();
    load_stage(1, 32); cp_commit();

    int st = 0;
    for (int kt = 0; kt < NK; kt++) {
        cp_wait1();
        __syncthreads();

        uint32_t base = sb + (uint32_t)st * STAGE_BYTES;
        uint32_t aHiB = base +         (uint32_t)aRow * 64;
        uint32_t aLoB = aHiB + 8192;
        uint32_t bHiB = base + 16384 + (uint32_t)bRow * 64;
        uint32_t bLoB = bHiB + 8192;

#pragma unroll
        for (int k = 0; k < 2; k++) {
            const uint32_t ka = ((2u * k + aCH) ^ aSw) << 4;
            const uint32_t kb = ((2u * k + bCH) ^ bSw) << 4;
            // B fragments once per k-half (16 regs live)
            uint32_t bhi[2][4], blo[2][4];
#pragma unroll
            for (int p = 0; p < 2; p++) {
                ldsm4(bhi[p], bHiB + p * 1024 + kb);
                ldsm4(blo[p], bLoB + p * 1024 + kb);
            }
            // stream A fragments per mt (8 regs live)
#pragma unroll
            for (int mt = 0; mt < 4; mt++) {
                uint32_t ahi[4], alo[4];
                ldsm4(ahi, aHiB + mt * 1024 + ka);
                ldsm4(alo, aLoB + mt * 1024 + ka);
#pragma unroll
                for (int nt = 0; nt < 4; nt++) {
                    const uint32_t* bh2 = &bhi[nt >> 1][(nt & 1) * 2];
                    mma_bf16(acc[mt][nt], ahi, bh2);
                    mma_bf16(acc[mt][nt], ahi, &blo[nt >> 1][(nt & 1) * 2]);
                    mma_bf16(acc[mt][nt], alo, bh2);
                }
            }
        }

        if (kt + 2 < NK) load_stage((st + 2) % GSTAGES, (kt + 2) * 32);
        cp_commit();
        st = (st + 1) % GSTAGES;
    }

    const int g  = lane >> 2;
    const int i4 = lane & 3;
#pragma unroll
    for (int mt = 0; mt < 4; mt++) {
        int r = row0 + wm * 64 + mt * 16 + g;
#pragma unroll
        for (int nt = 0; nt < 4; nt++) {
            int c = col0 + wn * 32 + nt * 8 + i4 * 2;
            float2 bv = *(const float2*)(bias + c);
            size_t o0 = (size_t)r * N + c;
            size_t o1 = (size_t)(r + 8) * N + c;
            float2 v0, v1;
            v0.x = acc[mt][nt][0] + bv.x; v0.y = acc[mt][nt][1] + bv.y;
            v1.x = acc[mt][nt][2] + bv.x; v1.y = acc[mt][nt][3] + bv.y;
            if (RES) {
                float2 r0 = *(const float2*)(res + o0);
                float2 r1 = *(const float2*)(res + o1);
                v0.x += r0.x; v0.y += r0.y;
                v1.x += r1.x; v1.y += r1.y;
            }
            *(float2*)(C + o0) = v0;
            *(float2*)(C + o1) = v1;
        }
    }
}

// ============================================================
// FA2-style attention on mma.sync, split-bf16 3-term.
// CTA: q-tile 128 (8 warps x m16), kv-tile 64.
// ============================================================
#define AQ_OFF   0u
#define AQL_OFF  32768u
#define AK_OFF   65536u
#define AKL_OFF  81920u
#define AV_OFF   98304u
#define AVL_OFF  114688u
#define AAL_OFF  131072u
#define ATTN_SMEM (131072 + 256)

__device__ __forceinline__ void store_split8(uint32_t baseH, uint32_t baseL,
                                             int r, int d, float4 v)
{
    uint32_t h01 = pack_bf16(v.x, v.y);
    uint32_t h23 = pack_bf16(v.z, v.w);
    float2 f01 = unpack_bf16(h01);
    float2 f23 = unpack_bf16(h23);
    uint32_t l01 = pack_bf16(v.x - f01.x, v.y - f01.y);
    uint32_t l23 = pack_bf16(v.z - f23.x, v.w - f23.y);
    uint32_t off = (uint32_t)r * 256 + ((((uint32_t)d >> 3) ^ ((uint32_t)r & 7)) << 4)
                 + (((uint32_t)d & 4) << 1);
    asm volatile("st.shared.v2.b32 [%0], {%1,%2};" :: "r"(baseH + off), "r"(h01), "r"(h23));
    asm volatile("st.shared.v2.b32 [%0], {%1,%2};" :: "r"(baseL + off), "r"(l01), "r"(l23));
}

__global__ __launch_bounds__(256, 1)
void attn_mma(const float* __restrict__ qkv, const float* __restrict__ alibi,
              __nv_bfloat16* __restrict__ Ch, __nv_bfloat16* __restrict__ Cl)
{
    extern __shared__ __align__(1024) char sm[];
    const uint32_t sb = smem_u32(sm);
    const uint32_t Qh = sb + AQ_OFF,  Ql = sb + AQL_OFF;
    const uint32_t Kh = sb + AK_OFF,  Kl = sb + AKL_OFF;
    const uint32_t Vh = sb + AV_OFF,  Vl = sb + AVL_OFF;
    float* al_s = (float*)(sm + AAL_OFF);

    const int qt   = (int)gridDim.x - 1 - (int)blockIdx.x;  // heavy tiles first
    const int bh   = blockIdx.y;
    const int b    = bh >> 5;
    const int h    = bh & 31;
    const int tid  = threadIdx.x;
    const int lane = tid & 31;
    const int warp = tid >> 5;

    const size_t rowbase = (size_t)b * S_;
    const int qcol = h * 384;
    const float* al = alibi + (size_t)bh * S_;
    const float inv = 0.08838834764831845f;

    // ---- load Q tile [128][128] fp32 -> split -> smem ----
#pragma unroll 4
    for (int it = 0; it < 16; it++) {
        int r = it * 8 + warp;
        int d = lane * 4;
        float4 v = *(const float4*)(qkv + (rowbase + qt * 128 + r) * NQKV_ + qcol + d);
        store_split8(Qh, Ql, r, d, v);
    }

    const int aRow = warp * 16 + (lane & 15);
    const uint32_t aChH = (uint32_t)(lane >> 4);
    const int bRowBase = (((lane >> 4) & 1) << 3) + (lane & 7);
    const uint32_t bChH = (uint32_t)((lane >> 3) & 1);
    const int vTok = (lane & 7) + (lane & 8);
    const int vD   = (lane >> 4) << 3;

    const int g  = lane >> 2;
    const int c2 = (lane & 3) * 2;
    const int qg0 = qt * 128 + warp * 16 + g;

    float O[16][4];
#pragma unroll
    for (int n = 0; n < 16; n++)
#pragma unroll
        for (int e = 0; e < 4; e++) O[n][e] = 0.f;
    float m0 = -1e30f, m1 = -1e30f, l0 = 0.f, l1 = 0.f;

    const int jmax = 2 * qt + 1;
    for (int j = 0; j <= jmax; j++) {
        __syncthreads();
#pragma unroll 4
        for (int it = 0; it < 8; it++) {
            int r = it * 8 + warp;
            int d = lane * 4;
            const float* src = qkv + (rowbase + j * 64 + r) * NQKV_ + qcol + d;
            float4 kv4 = *(const float4*)(src + 128);
            float4 vv4 = *(const float4*)(src + 256);
            store_split8(Kh, Kl, r, d, kv4);
            store_split8(Vh, Vl, r, d, vv4);
        }
        if (tid < 16) ((float4*)al_s)[tid] = *(const float4*)(al + j * 64 + tid * 4);
        __syncthreads();

        float S[8][4];
#pragma unroll
        for (int n = 0; n < 8; n++)
#pragma unroll
            for (int e = 0; e < 4; e++) S[n][e] = 0.f;

#pragma unroll
        for (int ks = 0; ks < 8; ks++) {
            uint32_t aOff = (uint32_t)aRow * 256 +
                (((2u * ks + aChH) ^ ((uint32_t)aRow & 7)) << 4);
            uint32_t ahi[4], alo[4];
            ldsm4(ahi, Qh + aOff);
            ldsm4(alo, Ql + aOff);
#pragma unroll
            for (int p = 0; p < 4; p++) {
                int bRow = p * 16 + bRowBase;
                uint32_t bOff = (uint32_t)bRow * 256 +
                    (((2u * ks + bChH) ^ ((uint32_t)bRow & 7)) << 4);
                uint32_t bhi[4], blo[4];
                ldsm4(bhi, Kh + bOff);
                ldsm4(blo, Kl + bOff);
#pragma unroll
                for (int q2 = 0; q2 < 2; q2++) {
                    int nt = p * 2 + q2;
                    mma_bf16(S[nt], ahi, &bhi[q2 * 2]);
                    mma_bf16(S[nt], ahi, &blo[q2 * 2]);
                    mma_bf16(S[nt], alo, &bhi[q2 * 2]);
                }
            }
        }

        const bool diag = (j * 64 + 63 > qt * 128 + warp * 16);
#pragma unroll
        for (int nt = 0; nt < 8; nt++) {
            float a0 = al_s[nt * 8 + c2];
            float a1 = al_s[nt * 8 + c2 + 1];
            S[nt][0] = S[nt][0] * inv + a0;
            S[nt][1] = S[nt][1] * inv + a1;
            S[nt][2] = S[nt][2] * inv + a0;
            S[nt][3] = S[nt][3] * inv + a1;
            if (diag) {
                int kg = j * 64 + nt * 8 + c2;
                if (kg     > qg0)     S[nt][0] = -1e30f;
                if (kg + 1 > qg0)     S[nt][1] = -1e30f;
                if (kg     > qg0 + 8) S[nt][2] = -1e30f;
                if (kg + 1 > qg0 + 8) S[nt][3] = -1e30f;
            }
        }

        float mx0 = -1e30f, mx1 = -1e30f;
#pragma unroll
        for (int nt = 0; nt < 8; nt++) {
            mx0 = fmaxf(mx0, fmaxf(S[nt][0], S[nt][1]));
            mx1 = fmaxf(mx1, fmaxf(S[nt][2], S[nt][3]));
        }
        mx0 = fmaxf(mx0, __shfl_xor_sync(0xffffffffu, mx0, 1));
        mx0 = fmaxf(mx0, __shfl_xor_sync(0xffffffffu, mx0, 2));
        mx1 = fmaxf(mx1, __shfl_xor_sync(0xffffffffu, mx1, 1));
        mx1 = fmaxf(mx1, __shfl_xor_sync(0xffffffffu, mx1, 2));
        float mn0 = fmaxf(m0, mx0), mn1 = fmaxf(m1, mx1);
        float sf0 = __expf(m0 - mn0), sf1 = __expf(m1 - mn1);
        float sum0 = 0.f, sum1 = 0.f;
#pragma unroll
        for (int nt = 0; nt < 8; nt++) {
            S[nt][0] = __expf(S[nt][0] - mn0); sum0 += S[nt][0];
            S[nt][1] = __expf(S[nt][1] - mn0); sum0 += S[nt][1];
            S[nt][2] = __expf(S[nt][2] - mn1); sum1 += S[nt][2];
            S[nt][3] = __expf(S[nt][3] - mn1); sum1 += S[nt][3];
        }
        sum0 += __shfl_xor_sync(0xffffffffu, sum0, 1);
        sum0 += __shfl_xor_sync(0xffffffffu, sum0, 2);
        sum1 += __shfl_xor_sync(0xffffffffu, sum1, 1);
        sum1 += __shfl_xor_sync(0xffffffffu, sum1, 2);
        l0 = l0 * sf0 + sum0; m0 = mn0;
        l1 = l1 * sf1 + sum1; m1 = mn1;
#pragma unroll
        for (int n = 0; n < 16; n++) {
            O[n][0] *= sf0; O[n][1] *= sf0;
            O[n][2] *= sf1; O[n][3] *= sf1;
        }

#pragma unroll
        for (int ks = 0; ks < 4; ks++) {
            uint32_t pa_hi[4], pa_lo[4];
            {
                float x0 = S[2 * ks][0],     x1 = S[2 * ks][1];
                float x2 = S[2 * ks][2],     x3 = S[2 * ks][3];
                float y0 = S[2 * ks + 1][0], y1 = S[2 * ks + 1][1];
                float y2 = S[2 * ks + 1][2], y3 = S[2 * ks + 1][3];
                pa_hi[0] = pack_bf16(x0, x1);
                pa_hi[1] = pack_bf16(x2, x3);
                pa_hi[2] = pack_bf16(y0, y1);
                pa_hi[3] = pack_bf16(y2, y3);
                float2 u;
                u = unpack_bf16(pa_hi[0]); pa_lo[0] = pack_bf16(x0 - u.x, x1 - u.y);
                u = unpack_bf16(pa_hi[1]); pa_lo[1] = pack_bf16(x2 - u.x, x3 - u.y);
                u = unpack_bf16(pa_hi[2]); pa_lo[2] = pack_bf16(y0 - u.x, y1 - u.y);
                u = unpack_bf16(pa_hi[3]); pa_lo[3] = pack_bf16(y2 - u.x, y3 - u.y);
            }
            int tok = ks * 16 + vTok;
            uint32_t tRow = (uint32_t)tok * 256;
            uint32_t tSw  = (uint32_t)tok & 7;
#pragma unroll
            for (int nt16 = 0; nt16 < 8; nt16++) {
                int d = nt16 * 16 + vD;
                uint32_t vOff = tRow + ((((uint32_t)d >> 3) ^ tSw) << 4);
                uint32_t bvh[4], bvl[4];
                ldsm4t(bvh, Vh + vOff);
                ldsm4t(bvl, Vl + vOff);
                mma_bf16(O[nt16 * 2],     pa_hi, &bvh[0]);
                mma_bf16(O[nt16 * 2 + 1], pa_hi, &bvh[2]);
                mma_bf16(O[nt16 * 2],     pa_hi, &bvl[0]);
                mma_bf16(O[nt16 * 2 + 1], pa_hi, &bvl[2]);
                mma_bf16(O[nt16 * 2],     pa_lo, &bvh[0]);
                mma_bf16(O[nt16 * 2 + 1], pa_lo, &bvh[2]);
            }
        }
    }

    float il0 = 1.f / l0, il1 = 1.f / l1;
    size_t r0 = rowbase + qt * 128 + warp * 16 + g;
    size_t r1 = r0 + 8;
#pragma unroll
    for (int n = 0; n < 16; n++) {
        int col = h * 128 + n * 8 + c2;
        float o00 = O[n][0] * il0, o01 = O[n][1] * il0;
        float o10 = O[n][2] * il1, o11 = O[n][3] * il1;
        uint32_t h0 = pack_bf16(o00, o01);
        uint32_t h1 = pack_bf16(o10, o11);
        float2 u0 = unpack_bf16(h0);
        float2 u1 = unpack_bf16(h1);
        uint32_t lo0 = pack_bf16(o00 - u0.x, o01 - u0.y);
        uint32_t lo1 = pack_bf16(o10 - u1.x, o11 - u1.y);
        *(uint32_t*)(Ch + r0 * H_ + col) = h0;
        *(uint32_t*)(Cl + r0 * H_ + col) = lo0;
        *(uint32_t*)(Ch + r1 * H_ + col) = h1;
        *(uint32_t*)(Cl + r1 * H_ + col) = lo1;
    }
}

// ============================================================
// Launch
// ============================================================
extern "C" void kernel_launch(void* const* d_in, const int* in_sizes, int n_in,
                              void* d_out, int out_size)
{
    const float* hidden   = (const float*)d_in[0];
    const float* residual = (const float*)d_in[1];
    const float* alibi    = (const float*)d_in[2];
    const float* Wqkv     = (const float*)d_in[4];
    const float* bqkv     = (const float*)d_in[5];
    const float* Wd       = (const float*)d_in[6];
    const float* bd       = (const float*)d_in[7];
    float* out = (float*)d_out;

    void* p;
    cudaGetSymbolAddress(&p, g_qkv); float* qkv = (float*)p;
    cudaGetSymbolAddress(&p, g_Ah);  __nv_bfloat16* Ah  = (__nv_bfloat16*)p;
    cudaGetSymbolAddress(&p, g_Al);  __nv_bfloat16* Al  = (__nv_bfloat16*)p;
    cudaGetSymbolAddress(&p, g_Bqh); __nv_bfloat16* Bqh = (__nv_bfloat16*)p;
    cudaGetSymbolAddress(&p, g_Bql); __nv_bfloat16* Bql = (__nv_bfloat16*)p;
    cudaGetSymbolAddress(&p, g_Bdh); __nv_bfloat16* Bdh = (__nv_bfloat16*)p;
    cudaGetSymbolAddress(&p, g_Bdl); __nv_bfloat16* Bdl = (__nv_bfloat16*)p;
    cudaGetSymbolAddress(&p, g_Ch);  __nv_bfloat16* Ch  = (__nv_bfloat16*)p;
    cudaGetSymbolAddress(&p, g_Cl);  __nv_bfloat16* Cl  = (__nv_bfloat16*)p;

    cudaFuncSetAttribute(attn_mma, cudaFuncAttributeMaxDynamicSharedMemorySize, ATTN_SMEM);
    cudaFuncSetAttribute(mma_gemm<false>, cudaFuncAttributeMaxDynamicSharedMemorySize, GSM_TOTAL);
    cudaFuncSetAttribute(mma_gemm<true>,  cudaFuncAttributeMaxDynamicSharedMemorySize, GSM_TOTAL);

    // 0) split inputs to bf16 hi/lo
    split_rows<<<(M_ * H_ / 4 + 255) / 256, 256>>>(hidden, Ah, Al, M_ * H_ / 4);
    split_transpose<<<dim3(NQKV_ / 32, H_ / 32), dim3(32, 8)>>>(Wqkv, Bqh, Bql, H_, NQKV_);
    split_transpose<<<dim3(H_ / 32, H_ / 32), dim3(32, 8)>>>(Wd, Bdh, Bdl, H_, H_);

    // 1) QKV projection
    mma_gemm<false><<<dim3(M_ / 128, NQKV_ / 128), 256, GSM_TOTAL>>>(
        Ah, Al, Bqh, Bql, bqkv, nullptr, qkv, NQKV_, H_);

    // 2) attention -> ctx (bf16 hi/lo, directly consumable by dense GEMM)
    attn_mma<<<dim3(S_ / 128, B_ * NH_), 256, ATTN_SMEM>>>(qkv, alibi, Ch, Cl);

    // 3) dense projection + bias + residual
    mma_gemm<true><<<dim3(M_ / 128, H_ / 128), 256, GSM_TOTAL>>>(
        Ch, Cl, Bdh, Bdl, bd, residual, out, H_, H_);
}